// round 1
// baseline (speedup 1.0000x reference)
#include <cuda_runtime.h>
#include <math.h>

#define BSZ 8
#define SRC 512
#define TGT 256
#define HID 1024
#define TV 15000
#define VOC 20000
#define S1 513
#define NROWS (BSZ*TGT)

#define EPSF 1.1920929e-7f
#define LOG_EPS -15.942385f
#define NEG_BIG -1000000000.0f

// ---------------- scratch (device globals; no allocation allowed) ----------
__device__ float g_Q[NROWS * HID];      // gelu(feature @ W_q^T + b)
__device__ float g_att[NROWS * S1];     // raw scaled+masked attention scores
__device__ float g_prob[NROWS * S1];    // softmax probs (s<512 used)
__device__ float2 g_rowc[NROWS];        // {gate_logprob g, D = L2 - L1}

// ---------------- K1: Q = gelu(feature @ W_q^T + b_q) ----------------------
// A: feature [2048,1024] row-major, B: W_q [1024,1024] row-major (N x K)
// 128x128x8 tile, 256 threads, 8x8 microtile.
__global__ __launch_bounds__(256) void k1_gemm_gelu(
    const float* __restrict__ A, const float* __restrict__ B,
    const float* __restrict__ bias) {
  __shared__ float As[8][128];
  __shared__ float Bs[8][128];
  int tid = threadIdx.x;
  int m0 = blockIdx.y * 128;
  int n0 = blockIdx.x * 128;
  int lr = tid >> 1;           // 0..127
  int lk = (tid & 1) * 4;      // 0 or 4
  int tm = (tid >> 4) * 8;
  int tn = (tid & 15) * 8;

  float acc[8][8];
#pragma unroll
  for (int i = 0; i < 8; i++)
#pragma unroll
    for (int j = 0; j < 8; j++) acc[i][j] = 0.f;

  const float* Ap = A + (size_t)(m0 + lr) * HID + lk;
  const float* Bp = B + (size_t)(n0 + lr) * HID + lk;

  for (int k0 = 0; k0 < HID; k0 += 8) {
    float4 av = *(const float4*)(Ap + k0);
    float4 bv = *(const float4*)(Bp + k0);
    As[lk + 0][lr] = av.x; As[lk + 1][lr] = av.y;
    As[lk + 2][lr] = av.z; As[lk + 3][lr] = av.w;
    Bs[lk + 0][lr] = bv.x; Bs[lk + 1][lr] = bv.y;
    Bs[lk + 2][lr] = bv.z; Bs[lk + 3][lr] = bv.w;
    __syncthreads();
#pragma unroll
    for (int k = 0; k < 8; k++) {
      float a[8], b[8];
#pragma unroll
      for (int i = 0; i < 8; i++) a[i] = As[k][tm + i];
#pragma unroll
      for (int j = 0; j < 8; j++) b[j] = Bs[k][tn + j];
#pragma unroll
      for (int i = 0; i < 8; i++)
#pragma unroll
        for (int j = 0; j < 8; j++) acc[i][j] = fmaf(a[i], b[j], acc[i][j]);
    }
    __syncthreads();
  }

#pragma unroll
  for (int i = 0; i < 8; i++) {
    int gm = m0 + tm + i;
#pragma unroll
    for (int j = 0; j < 8; j++) {
      int gn = n0 + tn + j;
      float x = acc[i][j] + bias[gn];
      // exact gelu: 0.5*x*(1+erf(x/sqrt(2)))
      float ge = 0.5f * x * (1.0f + erff(x * 0.70710678118654752f));
      g_Q[(size_t)gm * HID + gn] = ge;
    }
  }
}

// ---------------- K2: atten[b,t,s] = dot(Q[b,t], key[b,s]) / 32, masked ----
// key[b,s] = memory[b,s] for s<512, sentinel for s==512.
// per batch GEMM M=256 N=513 K=1024; 64x64x16 tiles, 256 threads, 4x4.
__global__ __launch_bounds__(256) void k2_atten(
    const float* __restrict__ memory, const float* __restrict__ sentinel,
    const unsigned char* __restrict__ mask) {
  __shared__ float As[16][64];
  __shared__ float Bs[16][64];
  int tid = threadIdx.x;
  int b = blockIdx.z;
  int m0 = blockIdx.y * 64;
  int n0 = blockIdx.x * 64;
  int lr = tid >> 2;           // 0..63
  int lk = (tid & 3) * 4;      // 0,4,8,12
  int tm = (tid >> 4) * 4;
  int tn = (tid & 15) * 4;

  float acc[4][4];
#pragma unroll
  for (int i = 0; i < 4; i++)
#pragma unroll
    for (int j = 0; j < 4; j++) acc[i][j] = 0.f;

  const float* Ap = g_Q + (size_t)(b * TGT + m0 + lr) * HID + lk;
  int n = n0 + lr;
  const float* Bp = (n < SRC)
      ? (memory + ((size_t)b * SRC + n) * HID + lk)
      : (sentinel + lk);
  bool bvalid = (n <= SRC);  // n==512 -> sentinel; n>512 -> zero fill

  for (int k0 = 0; k0 < HID; k0 += 16) {
    float4 av = *(const float4*)(Ap + k0);
    float4 bv = make_float4(0.f, 0.f, 0.f, 0.f);
    if (bvalid) bv = *(const float4*)(Bp + k0);
    As[lk + 0][lr] = av.x; As[lk + 1][lr] = av.y;
    As[lk + 2][lr] = av.z; As[lk + 3][lr] = av.w;
    Bs[lk + 0][lr] = bv.x; Bs[lk + 1][lr] = bv.y;
    Bs[lk + 2][lr] = bv.z; Bs[lk + 3][lr] = bv.w;
    __syncthreads();
#pragma unroll
    for (int k = 0; k < 16; k++) {
      float a[4], bb[4];
#pragma unroll
      for (int i = 0; i < 4; i++) a[i] = As[k][tm + i];
#pragma unroll
      for (int j = 0; j < 4; j++) bb[j] = Bs[k][tn + j];
#pragma unroll
      for (int i = 0; i < 4; i++)
#pragma unroll
        for (int j = 0; j < 4; j++) acc[i][j] = fmaf(a[i], bb[j], acc[i][j]);
    }
    __syncthreads();
  }

#pragma unroll
  for (int i = 0; i < 4; i++) {
    int t = m0 + tm + i;
#pragma unroll
    for (int j = 0; j < 4; j++) {
      int s = n0 + tn + j;
      if (s < S1) {
        float v = acc[i][j] * 0.03125f;  // 1/sqrt(1024)
        if (s < SRC && mask[b * SRC + s]) v = NEG_BIG;
        g_att[((size_t)(b * TGT + t)) * S1 + s] = v;
      }
    }
  }
}

// ---------------- K2b: per-row log-softmax over 513; store probs + consts --
__global__ __launch_bounds__(256) void k2b_softmax() {
  int row = blockIdx.x;
  const float* x = g_att + (size_t)row * S1;
  __shared__ float red[8];
  int tid = threadIdx.x, lane = tid & 31, wid = tid >> 5;

  float m = -3.4e38f;
  for (int i = tid; i < S1; i += 256) m = fmaxf(m, x[i]);
#pragma unroll
  for (int o = 16; o; o >>= 1) m = fmaxf(m, __shfl_xor_sync(0xffffffffu, m, o));
  if (lane == 0) red[wid] = m;
  __syncthreads();
  if (tid < 32) {
    float t = (lane < 8) ? red[lane] : -3.4e38f;
#pragma unroll
    for (int o = 16; o; o >>= 1) t = fmaxf(t, __shfl_xor_sync(0xffffffffu, t, o));
    if (lane == 0) red[0] = t;
  }
  __syncthreads();
  float M = red[0];
  __syncthreads();

  float s = 0.f;
  for (int i = tid; i < S1; i += 256) s += expf(x[i] - M);
#pragma unroll
  for (int o = 16; o; o >>= 1) s += __shfl_xor_sync(0xffffffffu, s, o);
  if (lane == 0) red[wid] = s;
  __syncthreads();
  if (tid < 32) {
    float t = (lane < 8) ? red[lane] : 0.f;
#pragma unroll
    for (int o = 16; o; o >>= 1) t += __shfl_xor_sync(0xffffffffu, t, o);
    if (lane == 0) red[0] = t;
  }
  __syncthreads();
  float S = red[0];
  float lse = M + logf(S);
  float inv = 1.0f / S;

  for (int i = tid; i < SRC; i += 256)
    g_prob[(size_t)row * S1 + i] = expf(x[i] - M) * inv;

  if (tid == 0) {
    float g = x[SRC] - lse;              // gate log-prob (sentinel slot)
    float eg = expf(g);
    float L1 = log1pf(EPSF - eg);        // log1p(-exp(g)+EPS)
    float L2 = logf(1.0f - eg + EPSF);   // log(1-exp(g)+EPS)
    g_rowc[row] = make_float2(g, L2 - L1);
  }
}

// ---------------- K3: fused log_softmax(logits) + scatter + logsumexp ------
// one block per (b,t); smem: logits row (15008 floats) + vocab acc (20000).
__global__ __launch_bounds__(1024) void k3_out(
    const float* __restrict__ logits, const int* __restrict__ content_e,
    float* __restrict__ out) {
  extern __shared__ float sm[];
  float* sLog = sm;          // 15008 (padded)
  float* sP = sm + 15008;    // 20000
  __shared__ float red[32];
  int row = blockIdx.x;
  int b = row >> 8;
  int tid = threadIdx.x, lane = tid & 31, wid = tid >> 5;

  const float* lg = logits + (size_t)row * TV;
  float m = -3.4e38f;
  for (int i = tid; i < TV; i += 1024) {
    float v = lg[i];
    sLog[i] = v;
    m = fmaxf(m, v);
  }
#pragma unroll
  for (int o = 16; o; o >>= 1) m = fmaxf(m, __shfl_xor_sync(0xffffffffu, m, o));
  if (lane == 0) red[wid] = m;
  __syncthreads();
  if (tid < 32) {
    float t = red[lane];
#pragma unroll
    for (int o = 16; o; o >>= 1) t = fmaxf(t, __shfl_xor_sync(0xffffffffu, t, o));
    if (lane == 0) red[0] = t;
  }
  __syncthreads();
  float M = red[0];
  __syncthreads();

  float s = 0.f;
  for (int i = tid; i < TV; i += 1024) s += expf(sLog[i] - M);
#pragma unroll
  for (int o = 16; o; o >>= 1) s += __shfl_xor_sync(0xffffffffu, s, o);
  if (lane == 0) red[wid] = s;
  __syncthreads();
  if (tid < 32) {
    float t = red[lane];
#pragma unroll
    for (int o = 16; o; o >>= 1) t += __shfl_xor_sync(0xffffffffu, t, o);
    if (lane == 0) red[0] = t;
  }
  __syncthreads();
  float lse = M + logf(red[0]);

  // zero vocab accumulator
  for (int i = tid; i < VOC; i += 1024) sP[i] = 0.f;
  __syncthreads();

  // scatter: p[v] += prob[s] where content_e[b,s]==v
  if (tid < SRC) {
    float p = g_prob[(size_t)row * S1 + tid];
    int v = content_e[b * SRC + tid];
    atomicAdd(&sP[v], p);
  }
  __syncthreads();

  float2 rc = g_rowc[row];
  float g = rc.x, D = rc.y;
  float c0 = LOG_EPS + D;  // pointer term when p==0
  float* op = out + (size_t)row * VOC;

  for (int v = tid; v < VOC; v += 1024) {
    float p = sP[v];
    float t2 = (p > 0.f) ? (logf(p + EPSF) + D) : c0;
    float o;
    if (v < TV) {
      float a = sLog[v] - lse + g;           // out_pad + gate
      float mx = fmaxf(a, t2);
      o = mx + log1pf(expf(-fabsf(a - t2))); // logaddexp
    } else {
      o = t2;                                // out_pad = -inf branch
    }
    op[v] = o;
  }
}

// ---------------- launch ---------------------------------------------------
extern "C" void kernel_launch(void* const* d_in, const int* in_sizes, int n_in,
                              void* d_out, int out_size) {
  const float* logits = (const float*)d_in[0];
  const float* feature = (const float*)d_in[1];
  const float* memory = (const float*)d_in[2];
  const float* W_q = (const float*)d_in[3];
  const float* b_q = (const float*)d_in[4];
  const float* sentinel = (const float*)d_in[5];
  const unsigned char* mask = (const unsigned char*)d_in[6];
  const int* content_e = (const int*)d_in[7];
  float* out = (float*)d_out;

  // K1: 2048x1024 = (16 x 8) tiles of 128x128
  k1_gemm_gelu<<<dim3(8, 16), 256>>>(feature, W_q, b_q);

  // K2: per batch 256x513, tiles 64x64 -> (9, 4, 8)
  k2_atten<<<dim3(9, 4, 8), 256>>>(memory, sentinel, mask);

  // K2b: one block per row
  k2b_softmax<<<NROWS, 256>>>();

  // K3: one block per row, 140032B dynamic smem
  const int smem3 = (15008 + VOC) * (int)sizeof(float);
  cudaFuncSetAttribute(k3_out, cudaFuncAttributeMaxDynamicSharedMemorySize, smem3);
  k3_out<<<NROWS, 1024, smem3>>>(logits, content_e, out);
}

// round 2
// speedup vs baseline: 1.4278x; 1.4278x over previous
#include <cuda_runtime.h>
#include <math.h>

#define BSZ 8
#define SRC 512
#define TGT 256
#define HID 1024
#define TV 15000
#define VOC 20000
#define S1 513
#define NROWS (BSZ*TGT)

#define EPSF 1.1920929e-7f
#define LOG_EPS -15.942385f
#define NEG_BIG -1000000000.0f

// ---------------- scratch (device globals; no allocation allowed) ----------
__device__ float g_Q[NROWS * HID];      // gelu(feature @ W_q^T + b)
__device__ float g_att[NROWS * S1];     // raw scaled+masked attention scores
__device__ float g_prob[NROWS * S1];    // softmax probs (s<512 used)
__device__ float2 g_rowc[NROWS];        // {gate_logprob g, D = L2 - L1}

// ---------------- K1: Q = gelu(feature @ W_q^T + b_q) ----------------------
// A: feature [2048,1024] row-major, B: W_q [1024,1024] row-major (N x K)
// 128x128 tile, K-tile 16, register double-buffered, 256 threads, 8x8 micro.
__global__ __launch_bounds__(256) void k1_gemm_gelu(
    const float* __restrict__ A, const float* __restrict__ B,
    const float* __restrict__ bias) {
  __shared__ float As[2][16][128];
  __shared__ float Bs[2][16][128];
  int tid = threadIdx.x;
  int m0 = blockIdx.y * 128;
  int n0 = blockIdx.x * 128;
  int lr = tid >> 1;           // 0..127
  int lk = (tid & 1) * 8;      // 0 or 8
  int tm = (tid >> 4) * 8;
  int tn = (tid & 15) * 8;

  float acc[8][8];
#pragma unroll
  for (int i = 0; i < 8; i++)
#pragma unroll
    for (int j = 0; j < 8; j++) acc[i][j] = 0.f;

  const float* Ap = A + (size_t)(m0 + lr) * HID + lk;
  const float* Bp = B + (size_t)(n0 + lr) * HID + lk;

  float4 a0, a1, b0, b1;
  // prologue: load k-tile 0
  a0 = *(const float4*)(Ap + 0);
  a1 = *(const float4*)(Ap + 4);
  b0 = *(const float4*)(Bp + 0);
  b1 = *(const float4*)(Bp + 4);
  {
    As[0][lk + 0][lr] = a0.x; As[0][lk + 1][lr] = a0.y;
    As[0][lk + 2][lr] = a0.z; As[0][lk + 3][lr] = a0.w;
    As[0][lk + 4][lr] = a1.x; As[0][lk + 5][lr] = a1.y;
    As[0][lk + 6][lr] = a1.z; As[0][lk + 7][lr] = a1.w;
    Bs[0][lk + 0][lr] = b0.x; Bs[0][lk + 1][lr] = b0.y;
    Bs[0][lk + 2][lr] = b0.z; Bs[0][lk + 3][lr] = b0.w;
    Bs[0][lk + 4][lr] = b1.x; Bs[0][lk + 5][lr] = b1.y;
    Bs[0][lk + 6][lr] = b1.z; Bs[0][lk + 7][lr] = b1.w;
  }
  __syncthreads();

  const int NT = HID / 16;  // 64
  for (int kt = 0; kt < NT; kt++) {
    int cur = kt & 1;
    if (kt + 1 < NT) {
      int k0 = (kt + 1) * 16;
      a0 = *(const float4*)(Ap + k0);
      a1 = *(const float4*)(Ap + k0 + 4);
      b0 = *(const float4*)(Bp + k0);
      b1 = *(const float4*)(Bp + k0 + 4);
    }
#pragma unroll
    for (int k = 0; k < 16; k++) {
      float a[8], b[8];
#pragma unroll
      for (int i = 0; i < 8; i++) a[i] = As[cur][k][tm + i];
#pragma unroll
      for (int j = 0; j < 8; j++) b[j] = Bs[cur][k][tn + j];
#pragma unroll
      for (int i = 0; i < 8; i++)
#pragma unroll
        for (int j = 0; j < 8; j++) acc[i][j] = fmaf(a[i], b[j], acc[i][j]);
    }
    if (kt + 1 < NT) {
      int nxt = cur ^ 1;
      As[nxt][lk + 0][lr] = a0.x; As[nxt][lk + 1][lr] = a0.y;
      As[nxt][lk + 2][lr] = a0.z; As[nxt][lk + 3][lr] = a0.w;
      As[nxt][lk + 4][lr] = a1.x; As[nxt][lk + 5][lr] = a1.y;
      As[nxt][lk + 6][lr] = a1.z; As[nxt][lk + 7][lr] = a1.w;
      Bs[nxt][lk + 0][lr] = b0.x; Bs[nxt][lk + 1][lr] = b0.y;
      Bs[nxt][lk + 2][lr] = b0.z; Bs[nxt][lk + 3][lr] = b0.w;
      Bs[nxt][lk + 4][lr] = b1.x; Bs[nxt][lk + 5][lr] = b1.y;
      Bs[nxt][lk + 6][lr] = b1.z; Bs[nxt][lk + 7][lr] = b1.w;
      __syncthreads();
    }
  }

#pragma unroll
  for (int i = 0; i < 8; i++) {
    int gm = m0 + tm + i;
    float* orow = g_Q + (size_t)gm * HID + n0 + tn;
    float4 o4;
#pragma unroll
    for (int jj = 0; jj < 2; jj++) {
      float v[4];
#pragma unroll
      for (int j = 0; j < 4; j++) {
        int gn = n0 + tn + jj * 4 + j;
        float x = acc[i][jj * 4 + j] + bias[gn];
        v[j] = 0.5f * x * (1.0f + erff(x * 0.70710678118654752f));
      }
      o4 = make_float4(v[0], v[1], v[2], v[3]);
      *(float4*)(orow + jj * 4) = o4;
    }
  }
}

// ---------------- K2: atten[b,t,s] = dot(Q[b,t], key[b,s]) / 32, masked ----
// key[b,s] = memory[b,s] for s<512, sentinel for s==512.
// per batch GEMM M=256 N=513 K=1024; 128x64 tiles, K-tile 16, 8x4 micro.
__global__ __launch_bounds__(256) void k2_atten(
    const float* __restrict__ memory, const float* __restrict__ sentinel,
    const unsigned char* __restrict__ mask) {
  __shared__ float As[2][16][128];
  __shared__ float Bs[2][16][64];
  int tid = threadIdx.x;
  int b = blockIdx.z;
  int m0 = blockIdx.y * 128;
  int n0 = blockIdx.x * 64;
  int lrA = tid >> 1;           // 0..127
  int lkA = (tid & 1) * 8;      // 0 or 8
  int lrB = tid >> 2;           // 0..63
  int lkB = (tid & 3) * 4;      // 0,4,8,12
  int tm = (tid >> 4) * 8;
  int tn = (tid & 15) * 4;

  float acc[8][4];
#pragma unroll
  for (int i = 0; i < 8; i++)
#pragma unroll
    for (int j = 0; j < 4; j++) acc[i][j] = 0.f;

  const float* Ap = g_Q + (size_t)(b * TGT + m0 + lrA) * HID + lkA;
  int n = n0 + lrB;
  const float* Bp = (n < SRC)
      ? (memory + ((size_t)b * SRC + n) * HID + lkB)
      : (sentinel + lkB);
  bool bvalid = (n <= SRC);

  float4 a0, a1, bv;
  a0 = *(const float4*)(Ap + 0);
  a1 = *(const float4*)(Ap + 4);
  bv = bvalid ? *(const float4*)(Bp + 0) : make_float4(0.f, 0.f, 0.f, 0.f);
  {
    As[0][lkA + 0][lrA] = a0.x; As[0][lkA + 1][lrA] = a0.y;
    As[0][lkA + 2][lrA] = a0.z; As[0][lkA + 3][lrA] = a0.w;
    As[0][lkA + 4][lrA] = a1.x; As[0][lkA + 5][lrA] = a1.y;
    As[0][lkA + 6][lrA] = a1.z; As[0][lkA + 7][lrA] = a1.w;
    Bs[0][lkB + 0][lrB] = bv.x; Bs[0][lkB + 1][lrB] = bv.y;
    Bs[0][lkB + 2][lrB] = bv.z; Bs[0][lkB + 3][lrB] = bv.w;
  }
  __syncthreads();

  const int NT = HID / 16;
  for (int kt = 0; kt < NT; kt++) {
    int cur = kt & 1;
    if (kt + 1 < NT) {
      int k0 = (kt + 1) * 16;
      a0 = *(const float4*)(Ap + k0);
      a1 = *(const float4*)(Ap + k0 + 4);
      bv = bvalid ? *(const float4*)(Bp + k0) : make_float4(0.f, 0.f, 0.f, 0.f);
    }
#pragma unroll
    for (int k = 0; k < 16; k++) {
      float a[8], bb[4];
#pragma unroll
      for (int i = 0; i < 8; i++) a[i] = As[cur][k][tm + i];
#pragma unroll
      for (int j = 0; j < 4; j++) bb[j] = Bs[cur][k][tn + j];
#pragma unroll
      for (int i = 0; i < 8; i++)
#pragma unroll
        for (int j = 0; j < 4; j++) acc[i][j] = fmaf(a[i], bb[j], acc[i][j]);
    }
    if (kt + 1 < NT) {
      int nxt = cur ^ 1;
      As[nxt][lkA + 0][lrA] = a0.x; As[nxt][lkA + 1][lrA] = a0.y;
      As[nxt][lkA + 2][lrA] = a0.z; As[nxt][lkA + 3][lrA] = a0.w;
      As[nxt][lkA + 4][lrA] = a1.x; As[nxt][lkA + 5][lrA] = a1.y;
      As[nxt][lkA + 6][lrA] = a1.z; As[nxt][lkA + 7][lrA] = a1.w;
      Bs[nxt][lkB + 0][lrB] = bv.x; Bs[nxt][lkB + 1][lrB] = bv.y;
      Bs[nxt][lkB + 2][lrB] = bv.z; Bs[nxt][lkB + 3][lrB] = bv.w;
      __syncthreads();
    }
  }

#pragma unroll
  for (int i = 0; i < 8; i++) {
    int t = m0 + tm + i;
#pragma unroll
    for (int j = 0; j < 4; j++) {
      int s = n0 + tn + j;
      if (s < S1) {
        float v = acc[i][j] * 0.03125f;  // 1/sqrt(1024)
        if (s < SRC && mask[b * SRC + s]) v = NEG_BIG;
        g_att[((size_t)(b * TGT + t)) * S1 + s] = v;
      }
    }
  }
}

// ---------------- K2b: per-row log-softmax over 513; store probs + consts --
__global__ __launch_bounds__(256) void k2b_softmax() {
  int row = blockIdx.x;
  const float* x = g_att + (size_t)row * S1;
  __shared__ float red[8];
  int tid = threadIdx.x, lane = tid & 31, wid = tid >> 5;

  float m = -3.4e38f;
  for (int i = tid; i < S1; i += 256) m = fmaxf(m, x[i]);
#pragma unroll
  for (int o = 16; o; o >>= 1) m = fmaxf(m, __shfl_xor_sync(0xffffffffu, m, o));
  if (lane == 0) red[wid] = m;
  __syncthreads();
  if (tid < 32) {
    float t = (lane < 8) ? red[lane] : -3.4e38f;
#pragma unroll
    for (int o = 16; o; o >>= 1) t = fmaxf(t, __shfl_xor_sync(0xffffffffu, t, o));
    if (lane == 0) red[0] = t;
  }
  __syncthreads();
  float M = red[0];
  __syncthreads();

  float s = 0.f;
  for (int i = tid; i < S1; i += 256) s += __expf(x[i] - M);
#pragma unroll
  for (int o = 16; o; o >>= 1) s += __shfl_xor_sync(0xffffffffu, s, o);
  if (lane == 0) red[wid] = s;
  __syncthreads();
  if (tid < 32) {
    float t = (lane < 8) ? red[lane] : 0.f;
#pragma unroll
    for (int o = 16; o; o >>= 1) t += __shfl_xor_sync(0xffffffffu, t, o);
    if (lane == 0) red[0] = t;
  }
  __syncthreads();
  float S = red[0];
  float lse = M + __logf(S);
  float inv = 1.0f / S;

  for (int i = tid; i < SRC; i += 256)
    g_prob[(size_t)row * S1 + i] = __expf(x[i] - M) * inv;

  if (tid == 0) {
    float g = x[SRC] - lse;              // gate log-prob (sentinel slot)
    float eg = __expf(g);
    float L1 = log1pf(EPSF - eg);        // log1p(-exp(g)+EPS)
    float L2 = logf(1.0f - eg + EPSF);   // log(1-exp(g)+EPS)
    g_rowc[row] = make_float2(g, L2 - L1);
  }
}

// ---------------- K3: fused log_softmax(logits) + scatter + logsumexp ------
// one block per (b,t); smem: vocab acc only (80000B) -> 2 blocks/SM.
// logits row is re-read (stays L2-resident between passes).
__global__ __launch_bounds__(1024) void k3_out(
    const float* __restrict__ logits, const int* __restrict__ content_e,
    float* __restrict__ out) {
  extern __shared__ float sP[];  // 20000
  __shared__ float red[32];
  int row = blockIdx.x;
  int b = row >> 8;
  int tid = threadIdx.x, lane = tid & 31, wid = tid >> 5;

  const float* lg = logits + (size_t)row * TV;

  // pass 1: max  (zero sP interleaved to hide latency)
  float m = -3.4e38f;
  for (int i = tid; i < TV; i += 1024) m = fmaxf(m, lg[i]);
  for (int i = tid; i < VOC; i += 1024) sP[i] = 0.f;
#pragma unroll
  for (int o = 16; o; o >>= 1) m = fmaxf(m, __shfl_xor_sync(0xffffffffu, m, o));
  if (lane == 0) red[wid] = m;
  __syncthreads();
  if (tid < 32) {
    float t = red[lane];
#pragma unroll
    for (int o = 16; o; o >>= 1) t = fmaxf(t, __shfl_xor_sync(0xffffffffu, t, o));
    if (lane == 0) red[0] = t;
  }
  __syncthreads();
  float M = red[0];
  __syncthreads();

  // pass 2: sum exp (L2 hits)
  float s = 0.f;
  for (int i = tid; i < TV; i += 1024) s += __expf(lg[i] - M);
#pragma unroll
  for (int o = 16; o; o >>= 1) s += __shfl_xor_sync(0xffffffffu, s, o);
  if (lane == 0) red[wid] = s;
  __syncthreads();
  if (tid < 32) {
    float t = red[lane];
#pragma unroll
    for (int o = 16; o; o >>= 1) t += __shfl_xor_sync(0xffffffffu, t, o);
    if (lane == 0) red[0] = t;
  }
  __syncthreads();
  float lse = M + __logf(red[0]);

  // scatter: p[v] += prob[s] where content_e[b,s]==v
  if (tid < SRC) {
    float p = g_prob[(size_t)row * S1 + tid];
    int v = content_e[b * SRC + tid];
    atomicAdd(&sP[v], p);
  }
  __syncthreads();

  float2 rc = g_rowc[row];
  float off = rc.x - lse;  // gate - lse
  float D = rc.y;
  float c0 = LOG_EPS + D;  // pointer term when p==0
  float* op = out + (size_t)row * VOC;

  for (int v = tid; v < TV; v += 1024) {
    float p = sP[v];
    float t2 = (p > 0.f) ? (__logf(p + EPSF) + D) : c0;
    float a = lg[v] + off;                       // log_softmax + gate
    float mx = fmaxf(a, t2);
    op[v] = mx + __logf(1.0f + __expf(-fabsf(a - t2)));
  }
  for (int v = TV + tid; v < VOC; v += 1024) {
    float p = sP[v];
    op[v] = (p > 0.f) ? (__logf(p + EPSF) + D) : c0;
  }
}

// ---------------- launch ---------------------------------------------------
extern "C" void kernel_launch(void* const* d_in, const int* in_sizes, int n_in,
                              void* d_out, int out_size) {
  const float* logits = (const float*)d_in[0];
  const float* feature = (const float*)d_in[1];
  const float* memory = (const float*)d_in[2];
  const float* W_q = (const float*)d_in[3];
  const float* b_q = (const float*)d_in[4];
  const float* sentinel = (const float*)d_in[5];
  const unsigned char* mask = (const unsigned char*)d_in[6];
  const int* content_e = (const int*)d_in[7];
  float* out = (float*)d_out;

  // K1: 2048x1024 = (16 x 8) tiles of 128x128
  k1_gemm_gelu<<<dim3(8, 16), 256>>>(feature, W_q, b_q);

  // K2: per batch 256x513, tiles 128x64 -> (9, 2, 8)
  k2_atten<<<dim3(9, 2, 8), 256>>>(memory, sentinel, mask);

  // K2b: one block per row
  k2b_softmax<<<NROWS, 256>>>();

  // K3: one block per row, 80000B dynamic smem -> 2 blocks/SM
  const int smem3 = VOC * (int)sizeof(float);
  cudaFuncSetAttribute(k3_out, cudaFuncAttributeMaxDynamicSharedMemorySize, smem3);
  k3_out<<<NROWS, 1024, smem3>>>(logits, content_e, out);
}

// round 3
// speedup vs baseline: 2.4895x; 1.7436x over previous
#include <cuda_runtime.h>
#include <cuda_bf16.h>
#include <math.h>
#include <stdint.h>

#define BSZ 8
#define SRC 512
#define TGT 256
#define HID 1024
#define TV 15000
#define VOC 20000
#define S1 513
#define NROWS (BSZ*TGT)

#define EPSF 1.1920929e-7f
#define LOG_EPS -15.942385f
#define NEG_BIG -1000000000.0f

// ---------------- scratch (device globals; no allocation allowed) ----------
__device__ __nv_bfloat16 g_qhi[NROWS * HID];
__device__ __nv_bfloat16 g_qlo[NROWS * HID];
__device__ float g_att[NROWS * S1];

// ---------------- mma helper -----------------------------------------------
__device__ __forceinline__ void mma_bf16(float c[4], const uint32_t a[4],
                                         const uint32_t b[2]) {
  asm volatile(
      "mma.sync.aligned.m16n8k16.row.col.f32.bf16.bf16.f32 "
      "{%0,%1,%2,%3}, {%4,%5,%6,%7}, {%8,%9}, {%0,%1,%2,%3};"
      : "+f"(c[0]), "+f"(c[1]), "+f"(c[2]), "+f"(c[3])
      : "r"(a[0]), "r"(a[1]), "r"(a[2]), "r"(a[3]), "r"(b[0]), "r"(b[1]));
}

__device__ __forceinline__ uint32_t pack2(__nv_bfloat16 a, __nv_bfloat16 b) {
  return (uint32_t)__bfloat16_as_ushort(a) |
         ((uint32_t)__bfloat16_as_ushort(b) << 16);
}

// split float4 -> 4 hi bf16 (uint2) + 4 lo bf16 (uint2)
__device__ __forceinline__ void split4(float4 v, uint2& hi, uint2& lo) {
  __nv_bfloat16 h0 = __float2bfloat16(v.x);
  __nv_bfloat16 h1 = __float2bfloat16(v.y);
  __nv_bfloat16 h2 = __float2bfloat16(v.z);
  __nv_bfloat16 h3 = __float2bfloat16(v.w);
  __nv_bfloat16 l0 = __float2bfloat16(v.x - __bfloat162float(h0));
  __nv_bfloat16 l1 = __float2bfloat16(v.y - __bfloat162float(h1));
  __nv_bfloat16 l2 = __float2bfloat16(v.z - __bfloat162float(h2));
  __nv_bfloat16 l3 = __float2bfloat16(v.w - __bfloat162float(h3));
  hi.x = pack2(h0, h1); hi.y = pack2(h2, h3);
  lo.x = pack2(l0, l1); lo.y = pack2(l2, l3);
}

// ---------------- K1: Q = gelu(feature @ W_q^T + b_q), bf16 3-split mma ----
// block 128x128, 8 warps (2m x 4n), warp tile 64x32, k-tile 16, dbl-buffered.
__global__ __launch_bounds__(256, 1) void k1_mma(
    const float* __restrict__ A, const float* __restrict__ B,
    const float* __restrict__ bias) {
  __shared__ __nv_bfloat16 sA[2][2][128][24];
  __shared__ __nv_bfloat16 sB[2][2][128][24];
  const int tid = threadIdx.x;
  const int warp = tid >> 5, lane = tid & 31;
  const int m0 = blockIdx.y * 128, n0 = blockIdx.x * 128;
  const int wm = (warp >> 2) * 64, wn = (warp & 3) * 32;
  const int lr = lane >> 2, lc2 = (lane & 3) * 2;

  const int ldr = tid >> 2;        // 0..63
  const int ldc = (tid & 3) * 4;   // 0,4,8,12
  const float* pA0 = A + (size_t)(m0 + ldr) * HID + ldc;
  const float* pA1 = A + (size_t)(m0 + ldr + 64) * HID + ldc;
  const float* pB0 = B + (size_t)(n0 + ldr) * HID + ldc;
  const float* pB1 = B + (size_t)(n0 + ldr + 64) * HID + ldc;

  float acc[4][4][4];
#pragma unroll
  for (int i = 0; i < 4; i++)
#pragma unroll
    for (int j = 0; j < 4; j++)
#pragma unroll
      for (int k = 0; k < 4; k++) acc[i][j][k] = 0.f;

  float4 ra0 = *(const float4*)pA0;
  float4 ra1 = *(const float4*)pA1;
  float4 rb0 = *(const float4*)pB0;
  float4 rb1 = *(const float4*)pB1;

#define K1_STAGE(buf)                                                    \
  {                                                                      \
    uint2 h, l;                                                          \
    split4(ra0, h, l);                                                   \
    *(uint2*)&sA[buf][0][ldr][ldc] = h; *(uint2*)&sA[buf][1][ldr][ldc] = l; \
    split4(ra1, h, l);                                                   \
    *(uint2*)&sA[buf][0][ldr + 64][ldc] = h; *(uint2*)&sA[buf][1][ldr + 64][ldc] = l; \
    split4(rb0, h, l);                                                   \
    *(uint2*)&sB[buf][0][ldr][ldc] = h; *(uint2*)&sB[buf][1][ldr][ldc] = l; \
    split4(rb1, h, l);                                                   \
    *(uint2*)&sB[buf][0][ldr + 64][ldc] = h; *(uint2*)&sB[buf][1][ldr + 64][ldc] = l; \
  }

  K1_STAGE(0);
  __syncthreads();

  for (int kt = 0; kt < 64; kt++) {
    const int cur = kt & 1;
    if (kt < 63) {
      int off = (kt + 1) * 16;
      ra0 = *(const float4*)(pA0 + off);
      ra1 = *(const float4*)(pA1 + off);
      rb0 = *(const float4*)(pB0 + off);
      rb1 = *(const float4*)(pB1 + off);
    }
    uint32_t ah[4][4], al[4][4], bh[4][2], bl[4][2];
#pragma unroll
    for (int mi = 0; mi < 4; mi++) {
      int r = wm + mi * 16 + lr;
      ah[mi][0] = *(const uint32_t*)&sA[cur][0][r][lc2];
      ah[mi][1] = *(const uint32_t*)&sA[cur][0][r + 8][lc2];
      ah[mi][2] = *(const uint32_t*)&sA[cur][0][r][lc2 + 8];
      ah[mi][3] = *(const uint32_t*)&sA[cur][0][r + 8][lc2 + 8];
      al[mi][0] = *(const uint32_t*)&sA[cur][1][r][lc2];
      al[mi][1] = *(const uint32_t*)&sA[cur][1][r + 8][lc2];
      al[mi][2] = *(const uint32_t*)&sA[cur][1][r][lc2 + 8];
      al[mi][3] = *(const uint32_t*)&sA[cur][1][r + 8][lc2 + 8];
    }
#pragma unroll
    for (int ni = 0; ni < 4; ni++) {
      int r = wn + ni * 8 + lr;
      bh[ni][0] = *(const uint32_t*)&sB[cur][0][r][lc2];
      bh[ni][1] = *(const uint32_t*)&sB[cur][0][r][lc2 + 8];
      bl[ni][0] = *(const uint32_t*)&sB[cur][1][r][lc2];
      bl[ni][1] = *(const uint32_t*)&sB[cur][1][r][lc2 + 8];
    }
#pragma unroll
    for (int mi = 0; mi < 4; mi++)
#pragma unroll
      for (int ni = 0; ni < 4; ni++) {
        mma_bf16(acc[mi][ni], ah[mi], bh[ni]);
        mma_bf16(acc[mi][ni], ah[mi], bl[ni]);
        mma_bf16(acc[mi][ni], al[mi], bh[ni]);
      }
    if (kt < 63) {
      K1_STAGE((kt + 1) & 1);
      __syncthreads();
    }
  }

  // epilogue: bias + exact gelu + split-store qhi/qlo
#pragma unroll
  for (int mi = 0; mi < 4; mi++) {
#pragma unroll
    for (int ni = 0; ni < 4; ni++) {
      float* c = acc[mi][ni];
      int gm = m0 + wm + mi * 16 + lr;
      int gn = n0 + wn + ni * 8 + lc2;
      float b0v = bias[gn], b1v = bias[gn + 1];
#pragma unroll
      for (int half = 0; half < 2; half++) {
        int r = gm + half * 8;
        float x0 = c[half * 2 + 0] + b0v;
        float x1 = c[half * 2 + 1] + b1v;
        float g0 = 0.5f * x0 * (1.0f + erff(x0 * 0.70710678118654752f));
        float g1 = 0.5f * x1 * (1.0f + erff(x1 * 0.70710678118654752f));
        __nv_bfloat16 h0 = __float2bfloat16(g0);
        __nv_bfloat16 h1 = __float2bfloat16(g1);
        __nv_bfloat16 l0 = __float2bfloat16(g0 - __bfloat162float(h0));
        __nv_bfloat16 l1 = __float2bfloat16(g1 - __bfloat162float(h1));
        *(uint32_t*)&g_qhi[(size_t)r * HID + gn] = pack2(h0, h1);
        *(uint32_t*)&g_qlo[(size_t)r * HID + gn] = pack2(l0, l1);
      }
    }
  }
}

// ---------------- K2: atten = Q @ key^T / 32 (masked), bf16 3-split mma ----
// block 128x64 per batch, 8 warps (2m x 4n), warp tile 64x16.
__global__ __launch_bounds__(256, 1) void k2_mma(
    const float* __restrict__ memory, const float* __restrict__ sentinel,
    const unsigned char* __restrict__ mask) {
  __shared__ __nv_bfloat16 sA[2][2][128][24];
  __shared__ __nv_bfloat16 sB[2][2][64][24];
  const int tid = threadIdx.x;
  const int warp = tid >> 5, lane = tid & 31;
  const int b = blockIdx.z;
  const int m0 = blockIdx.y * 128;
  const int n0 = blockIdx.x * 64;
  const int rowbase = b * TGT + m0;
  const int wm = (warp >> 2) * 64, wn = (warp & 3) * 16;
  const int lr = lane >> 2, lc2 = (lane & 3) * 2;

  const int ldr = tid >> 2;
  const int ldc = (tid & 3) * 4;
  const __nv_bfloat16* qh0 = g_qhi + (size_t)(rowbase + ldr) * HID + ldc;
  const __nv_bfloat16* qh1 = g_qhi + (size_t)(rowbase + ldr + 64) * HID + ldc;
  const __nv_bfloat16* ql0 = g_qlo + (size_t)(rowbase + ldr) * HID + ldc;
  const __nv_bfloat16* ql1 = g_qlo + (size_t)(rowbase + ldr + 64) * HID + ldc;

  const int sgl = n0 + ldr;  // global key index this thread loads
  const float* kp = 0;
  if (sgl < SRC) kp = memory + ((size_t)b * SRC + sgl) * HID + ldc;
  else if (sgl == SRC) kp = sentinel + ldc;

  float acc[4][2][4];
#pragma unroll
  for (int i = 0; i < 4; i++)
#pragma unroll
    for (int j = 0; j < 2; j++)
#pragma unroll
      for (int k = 0; k < 4; k++) acc[i][j][k] = 0.f;

  uint2 rah0 = *(const uint2*)qh0;
  uint2 rah1 = *(const uint2*)qh1;
  uint2 ral0 = *(const uint2*)ql0;
  uint2 ral1 = *(const uint2*)ql1;
  float4 rbv = kp ? *(const float4*)kp : make_float4(0.f, 0.f, 0.f, 0.f);

#define K2_STAGE(buf)                                                     \
  {                                                                       \
    *(uint2*)&sA[buf][0][ldr][ldc] = rah0;                                \
    *(uint2*)&sA[buf][0][ldr + 64][ldc] = rah1;                           \
    *(uint2*)&sA[buf][1][ldr][ldc] = ral0;                                \
    *(uint2*)&sA[buf][1][ldr + 64][ldc] = ral1;                           \
    uint2 h, l;                                                           \
    split4(rbv, h, l);                                                    \
    *(uint2*)&sB[buf][0][ldr][ldc] = h;                                   \
    *(uint2*)&sB[buf][1][ldr][ldc] = l;                                   \
  }

  K2_STAGE(0);
  __syncthreads();

  for (int kt = 0; kt < 64; kt++) {
    const int cur = kt & 1;
    if (kt < 63) {
      int off = (kt + 1) * 16;
      rah0 = *(const uint2*)(qh0 + off);
      rah1 = *(const uint2*)(qh1 + off);
      ral0 = *(const uint2*)(ql0 + off);
      ral1 = *(const uint2*)(ql1 + off);
      rbv = kp ? *(const float4*)(kp + off) : make_float4(0.f, 0.f, 0.f, 0.f);
    }
    uint32_t ah[4][4], al[4][4], bh[2][2], bl[2][2];
#pragma unroll
    for (int mi = 0; mi < 4; mi++) {
      int r = wm + mi * 16 + lr;
      ah[mi][0] = *(const uint32_t*)&sA[cur][0][r][lc2];
      ah[mi][1] = *(const uint32_t*)&sA[cur][0][r + 8][lc2];
      ah[mi][2] = *(const uint32_t*)&sA[cur][0][r][lc2 + 8];
      ah[mi][3] = *(const uint32_t*)&sA[cur][0][r + 8][lc2 + 8];
      al[mi][0] = *(const uint32_t*)&sA[cur][1][r][lc2];
      al[mi][1] = *(const uint32_t*)&sA[cur][1][r + 8][lc2];
      al[mi][2] = *(const uint32_t*)&sA[cur][1][r][lc2 + 8];
      al[mi][3] = *(const uint32_t*)&sA[cur][1][r + 8][lc2 + 8];
    }
#pragma unroll
    for (int ni = 0; ni < 2; ni++) {
      int r = wn + ni * 8 + lr;
      bh[ni][0] = *(const uint32_t*)&sB[cur][0][r][lc2];
      bh[ni][1] = *(const uint32_t*)&sB[cur][0][r][lc2 + 8];
      bl[ni][0] = *(const uint32_t*)&sB[cur][1][r][lc2];
      bl[ni][1] = *(const uint32_t*)&sB[cur][1][r][lc2 + 8];
    }
#pragma unroll
    for (int mi = 0; mi < 4; mi++)
#pragma unroll
      for (int ni = 0; ni < 2; ni++) {
        mma_bf16(acc[mi][ni], ah[mi], bh[ni]);
        mma_bf16(acc[mi][ni], ah[mi], bl[ni]);
        mma_bf16(acc[mi][ni], al[mi], bh[ni]);
      }
    if (kt < 63) {
      K2_STAGE((kt + 1) & 1);
      __syncthreads();
    }
  }

#pragma unroll
  for (int mi = 0; mi < 4; mi++) {
#pragma unroll
    for (int ni = 0; ni < 2; ni++) {
      float* c = acc[mi][ni];
      int trow = rowbase + wm + mi * 16 + lr;
      int s0 = n0 + wn + ni * 8 + lc2;
#pragma unroll
      for (int half = 0; half < 2; half++) {
        int r = trow + half * 8;
#pragma unroll
        for (int jj = 0; jj < 2; jj++) {
          int s = s0 + jj;
          if (s < S1) {
            float v = c[half * 2 + jj] * 0.03125f;
            if (s < SRC && mask[b * SRC + s]) v = NEG_BIG;
            g_att[(size_t)r * S1 + s] = v;
          }
        }
      }
    }
  }
}

// ---------------- K3: att softmax + log_softmax(logits) + scatter + lse ----
__device__ __forceinline__ float laddexp(float a, float b) {
  float mx = fmaxf(a, b);
  return mx + __logf(1.0f + __expf(-fabsf(a - b)));
}

__global__ __launch_bounds__(1024) void k3_out(
    const float* __restrict__ logits, const int* __restrict__ content_e,
    float* __restrict__ out) {
  extern __shared__ float sP[];  // VOC floats
  __shared__ float satt[S1];
  __shared__ float2 redp[32];
  const int row = blockIdx.x, b = row >> 8;
  const int tid = threadIdx.x, lane = tid & 31, wid = tid >> 5;

  if (tid < S1) satt[tid] = g_att[(size_t)row * S1 + tid];

  const float4* lg4 = (const float4*)(logits + (size_t)row * TV);
  float4* sP4 = (float4*)sP;
  const float4 z4 = make_float4(0.f, 0.f, 0.f, 0.f);
  for (int i = tid; i < VOC / 4; i += 1024) sP4[i] = z4;

  // --- online lse over logits (single read pass) ---
  float m = -3.4e38f, sacc = 0.f;
  for (int i = tid; i < TV / 4; i += 1024) {
    float4 v = lg4[i];
    float mx = fmaxf(fmaxf(v.x, v.y), fmaxf(v.z, v.w));
    float mn = fmaxf(m, mx);
    sacc = sacc * __expf(m - mn) + __expf(v.x - mn) + __expf(v.y - mn) +
           __expf(v.z - mn) + __expf(v.w - mn);
    m = mn;
  }
#pragma unroll
  for (int o = 16; o; o >>= 1) {
    float m2 = __shfl_xor_sync(0xffffffffu, m, o);
    float s2 = __shfl_xor_sync(0xffffffffu, sacc, o);
    float mn = fmaxf(m, m2);
    sacc = sacc * __expf(m - mn) + s2 * __expf(m2 - mn);
    m = mn;
  }
  if (lane == 0) redp[wid] = make_float2(m, sacc);
  __syncthreads();
  if (tid < 32) {
    float2 q = redp[lane];
    m = q.x; sacc = q.y;
#pragma unroll
    for (int o = 16; o; o >>= 1) {
      float m2 = __shfl_xor_sync(0xffffffffu, m, o);
      float s2 = __shfl_xor_sync(0xffffffffu, sacc, o);
      float mn = fmaxf(m, m2);
      sacc = sacc * __expf(m - mn) + s2 * __expf(m2 - mn);
      m = mn;
    }
    if (lane == 0) redp[0] = make_float2(m, sacc);
  }
  __syncthreads();
  float2 MS = redp[0];
  const float lse = MS.x + __logf(MS.y);
  __syncthreads();

  // --- att lse over 513 (one element per thread) ---
  float ma = (tid < S1) ? satt[tid] : -3.4e38f;
  float sa = (tid < S1) ? 1.f : 0.f;
#pragma unroll
  for (int o = 16; o; o >>= 1) {
    float m2 = __shfl_xor_sync(0xffffffffu, ma, o);
    float s2 = __shfl_xor_sync(0xffffffffu, sa, o);
    float mn = fmaxf(ma, m2);
    sa = sa * __expf(ma - mn) + s2 * __expf(m2 - mn);
    ma = mn;
  }
  if (lane == 0) redp[wid] = make_float2(ma, sa);
  __syncthreads();
  if (tid < 32) {
    float2 q = redp[lane];
    ma = q.x; sa = q.y;
#pragma unroll
    for (int o = 16; o; o >>= 1) {
      float m2 = __shfl_xor_sync(0xffffffffu, ma, o);
      float s2 = __shfl_xor_sync(0xffffffffu, sa, o);
      float mn = fmaxf(ma, m2);
      sa = sa * __expf(ma - mn) + s2 * __expf(m2 - mn);
      ma = mn;
    }
    if (lane == 0) redp[0] = make_float2(ma, sa);
  }
  __syncthreads();
  float2 AS = redp[0];
  const float lseA = AS.x + __logf(AS.y);

  const float g = satt[SRC] - lseA;  // gate log-prob
  const float eg = __expf(g);
  const float D = logf(1.0f - eg + EPSF) - log1pf(EPSF - eg);
  const float off = g - lse;
  const float c0v = LOG_EPS + D;

  // --- scatter pointer probs ---
  if (tid < SRC) {
    float p = __expf(satt[tid] - lseA);
    atomicAdd(&sP[content_e[b * SRC + tid]], p);
  }
  __syncthreads();

  // --- output ---
  float4* op4 = (float4*)(out + (size_t)row * VOC);
  for (int i = tid; i < TV / 4; i += 1024) {
    float4 v = lg4[i];
    float4 p = sP4[i];
    float t0, t1, t2, t3;
    if (p.x > 0.f || p.y > 0.f || p.z > 0.f || p.w > 0.f) {
      t0 = __logf(p.x + EPSF) + D;
      t1 = __logf(p.y + EPSF) + D;
      t2 = __logf(p.z + EPSF) + D;
      t3 = __logf(p.w + EPSF) + D;
    } else {
      t0 = t1 = t2 = t3 = c0v;
    }
    float4 o;
    o.x = laddexp(v.x + off, t0);
    o.y = laddexp(v.y + off, t1);
    o.z = laddexp(v.z + off, t2);
    o.w = laddexp(v.w + off, t3);
    op4[i] = o;
  }
  for (int i = TV / 4 + tid; i < VOC / 4; i += 1024) {
    float4 p = sP4[i];
    float4 o;
    if (p.x > 0.f || p.y > 0.f || p.z > 0.f || p.w > 0.f) {
      o.x = (p.x > 0.f) ? (__logf(p.x + EPSF) + D) : c0v;
      o.y = (p.y > 0.f) ? (__logf(p.y + EPSF) + D) : c0v;
      o.z = (p.z > 0.f) ? (__logf(p.z + EPSF) + D) : c0v;
      o.w = (p.w > 0.f) ? (__logf(p.w + EPSF) + D) : c0v;
    } else {
      o = make_float4(c0v, c0v, c0v, c0v);
    }
    op4[i] = o;
  }
}

// ---------------- launch ---------------------------------------------------
extern "C" void kernel_launch(void* const* d_in, const int* in_sizes, int n_in,
                              void* d_out, int out_size) {
  const float* logits = (const float*)d_in[0];
  const float* feature = (const float*)d_in[1];
  const float* memory = (const float*)d_in[2];
  const float* W_q = (const float*)d_in[3];
  const float* b_q = (const float*)d_in[4];
  const float* sentinel = (const float*)d_in[5];
  const unsigned char* mask = (const unsigned char*)d_in[6];
  const int* content_e = (const int*)d_in[7];
  float* out = (float*)d_out;

  k1_mma<<<dim3(8, 16), 256>>>(feature, W_q, b_q);
  k2_mma<<<dim3(9, 2, 8), 256>>>(memory, sentinel, mask);

  const int smem3 = VOC * (int)sizeof(float);
  cudaFuncSetAttribute(k3_out, cudaFuncAttributeMaxDynamicSharedMemorySize,
                       smem3);
  k3_out<<<NROWS, 1024, smem3>>>(logits, content_e, out);
}